// round 16
// baseline (speedup 1.0000x reference)
#include <cuda_runtime.h>
#include <cuda_fp16.h>
#include <cstdint>

#define V_  32000
#define E_  512
#define H_  1024
#define B_  16
#define T_  256
#define BT  4096
#define FH  4096

// ---------------- scratch (device globals; no allocation allowed) -----------
__device__ float  g_zx[(size_t)BT * FH];                    // [t][b][4H] 64MB
__device__ __align__(16) __half g_hseq[(size_t)BT * H_];    // [b][t][H] fp16 8MB
__device__ __align__(16) __half g_hbuf[2][B_ * H_];         // double-buffered h
__device__ __align__(16) __half g_a16[(size_t)BT * E_];     // gathered emb fp16 4MB
__device__ __align__(16) __half g_wT[(size_t)FH * E_];      // kernel^T [4H,E]
__device__ __align__(16) __half g_woutT[(size_t)V_ * H_];   // w_out^T [V,H]
__device__ unsigned g_bar_count;

// ---------------- helpers ----------------------------------------------------
__device__ __forceinline__ uint32_t pack2h(float a, float b) {
    __half2 h = __floats2half2_rn(a, b);
    return *reinterpret_cast<uint32_t*>(&h);
}

__device__ __forceinline__ void mma_f16(float* c,
                                        uint32_t a0, uint32_t a1, uint32_t a2, uint32_t a3,
                                        uint32_t b0, uint32_t b1) {
    asm volatile(
        "mma.sync.aligned.m16n8k16.row.col.f32.f16.f16.f32 "
        "{%0,%1,%2,%3}, {%4,%5,%6,%7}, {%8,%9}, {%0,%1,%2,%3};"
        : "+f"(c[0]), "+f"(c[1]), "+f"(c[2]), "+f"(c[3])
        : "r"(a0), "r"(a1), "r"(a2), "r"(a3), "r"(b0), "r"(b1));
}

__device__ __forceinline__ void ldsm4(uint32_t& r0, uint32_t& r1, uint32_t& r2,
                                      uint32_t& r3, uint32_t addr) {
    asm volatile("ldmatrix.sync.aligned.m8n8.x4.shared.b16 {%0,%1,%2,%3}, [%4];"
                 : "=r"(r0), "=r"(r1), "=r"(r2), "=r"(r3) : "r"(addr));
}

__device__ __forceinline__ float tanhfast(float x) {
    float y;
    asm("tanh.approx.f32 %0, %1;" : "=f"(y) : "f"(x));
    return y;
}
__device__ __forceinline__ float sigfast(float x) {
    return fmaf(tanhfast(0.5f * x), 0.5f, 0.5f);
}

__device__ __forceinline__ void cp16(uint32_t dst, const void* src) {
    asm volatile("cp.async.cg.shared.global [%0], [%1], 16;\n" ::
                 "r"(dst), "l"(src) : "memory");
}
__device__ __forceinline__ void cp_commit() {
    asm volatile("cp.async.commit_group;" ::: "memory");
}
template <int N>
__device__ __forceinline__ void cp_wait() {
    asm volatile("cp.async.wait_group %0;" :: "n"(N) : "memory");
}

// ---------------- gathered embedding -> fp16 ----------------------------------
__global__ void __launch_bounds__(256)
gather_cvt(const int* __restrict__ xs, const float4* __restrict__ emb,
           uint2* __restrict__ dst) {
    int i = blockIdx.x * blockDim.x + threadIdx.x;   // 0 .. BT*E/4-1
    int r = i >> 7;             // row (E/4 = 128 float4s per row)
    int c = i & 127;
    int src = xs[(r & (B_ - 1)) * T_ + (r >> 4)];
    float4 v = emb[(size_t)src * (E_ / 4) + c];
    uint2 o;
    o.x = pack2h(v.x, v.y);
    o.y = pack2h(v.z, v.w);
    dst[i] = o;
}

// ---------------- fp32 [K,N] -> fp16 [N,K] transpose (for kernel W only) -------
__global__ void __launch_bounds__(256)
transpose_f16(const float* __restrict__ src, __half* __restrict__ dst, int K, int N) {
    __shared__ float tile[32][33];
    int n0 = blockIdx.x * 32, k0 = blockIdx.y * 32;
    int tx = threadIdx.x & 31, ty = threadIdx.x >> 5;  // 32 x 8
#pragma unroll
    for (int i = 0; i < 4; i++)
        tile[ty + i * 8][tx] = src[(size_t)(k0 + ty + i * 8) * N + n0 + tx];
    __syncthreads();
#pragma unroll
    for (int i = 0; i < 4; i++)
        dst[(size_t)(n0 + ty + i * 8) * K + k0 + tx] = __float2half_rn(tile[tx][ty + i * 8]);
}

// =============================================================================
// Pipelined fp16 GEMM (f32 accum), ldmatrix operand fetch. (R8/R10 config)
//   C[M,N] = A[M,K] @ Bt[N,K]^T + bias[N]
// CTA tile 128x128, k-tile 64, PS=3, 256 threads = 8 warps (2m x 4n of 64x32).
// 2 CTAs/SM. blockIdx.x = m (fast).
// =============================================================================
#define GTM 128
#define GTN 128
#define GTK 64
#define PS  3
#define A_BYTES (128 * 128)              // 16KB
#define ST_BYTES (2 * A_BYTES)           // 32KB
#define GEMM_SMEM (PS * ST_BYTES)        // 98304 B

__global__ void __launch_bounds__(256, 2)
gemm_ld(const uint32_t* __restrict__ A, const uint32_t* __restrict__ Bt,
        const float* __restrict__ bias, float* __restrict__ C,
        int M, int N, int K) {
    extern __shared__ uint32_t sm[];
    uint32_t sb;
    asm("{.reg .u64 t; cvta.to.shared.u64 t, %1; cvt.u32.u64 %0, t;}"
        : "=r"(sb) : "l"(sm));

    const int tid  = threadIdx.x;
    const int lane = tid & 31;
    const int wid  = tid >> 5;
    const int m0   = blockIdx.x * GTM;
    const int n0   = blockIdx.y * GTN;
    const int wm   = (wid & 1) * 64;
    const int wn   = (wid >> 1) * 32;
    const int g    = lane >> 2;
    const int tg   = lane & 3;
    const int Kw   = K >> 1;              // 32-bit words per row

    float acc[4][4][4];
#pragma unroll
    for (int i = 0; i < 4; i++)
#pragma unroll
        for (int j = 0; j < 4; j++)
#pragma unroll
            for (int k = 0; k < 4; k++) acc[i][j][k] = 0.0f;

    const int lr = tid >> 3;      // base row 0..31 (stride 32)
    const int lc = tid & 7;       // chunk 0..7
    const uint32_t sw_off = (uint32_t)(lr * 128 + ((lc ^ (lr & 7)) * 16));

    const uint32_t* aptr[4];
#pragma unroll
    for (int i = 0; i < 4; i++)
        aptr[i] = A + (size_t)(m0 + lr + i * 32) * Kw + lc * 4;
    const uint32_t* bptr = Bt + (size_t)(n0 + lr) * Kw + lc * 4;
    const size_t bstep = (size_t)32 * Kw;

    const int KT = K / GTK;

    auto load_stage = [&](int st, int kt) {
        const int k0w = kt * (GTK / 2);
        const uint32_t ab = sb + st * ST_BYTES + sw_off;
        const uint32_t bb = ab + A_BYTES;
#pragma unroll
        for (int i = 0; i < 4; i++) cp16(ab + i * 32 * 128, aptr[i] + k0w);
        const uint32_t* bp = bptr + k0w;
#pragma unroll
        for (int i = 0; i < 4; i++) { cp16(bb + i * 32 * 128, bp); bp += bstep; }
    };

    const int l7 = lane & 7;
    const int hb = (lane >> 3) & 1;
    const int hc = lane >> 4;
    uint32_t a_row_off[4], b_row_off[2];
#pragma unroll
    for (int mt = 0; mt < 4; mt++)
        a_row_off[mt] = (uint32_t)((wm + mt * 16 + l7 + hb * 8) * 128);
#pragma unroll
    for (int p = 0; p < 2; p++)
        b_row_off[p] = (uint32_t)(A_BYTES + (wn + p * 16 + l7 + hb * 8) * 128);
    uint32_t choff[4];
#pragma unroll
    for (int kk = 0; kk < 4; kk++)
        choff[kk] = (uint32_t)((((2 * kk + hc) ^ l7)) * 16);

#pragma unroll
    for (int p = 0; p < PS - 1; ++p) {
        load_stage(p, p);
        cp_commit();
    }

    for (int kt = 0; kt < KT; ++kt) {
        cp_wait<PS - 2>();
        __syncthreads();
        if (kt + PS - 1 < KT) load_stage((kt + PS - 1) % PS, kt + PS - 1);
        cp_commit();

        const uint32_t st = sb + (uint32_t)(kt % PS) * ST_BYTES;
#pragma unroll
        for (int kk = 0; kk < 4; kk++) {   // each kk = 16 K-elements
            const uint32_t co = choff[kk];
            uint32_t bf[4][2];
            ldsm4(bf[0][0], bf[1][0], bf[0][1], bf[1][1], st + b_row_off[0] + co);
            ldsm4(bf[2][0], bf[3][0], bf[2][1], bf[3][1], st + b_row_off[1] + co);
#pragma unroll
            for (int mt = 0; mt < 4; mt++) {
                uint32_t a0, a1, a2, a3;
                ldsm4(a0, a1, a2, a3, st + a_row_off[mt] + co);
#pragma unroll
                for (int nt = 0; nt < 4; nt++)
                    mma_f16(acc[mt][nt], a0, a1, a2, a3, bf[nt][0], bf[nt][1]);
            }
        }
    }

#pragma unroll
    for (int mt = 0; mt < 4; mt++) {
#pragma unroll
        for (int nt = 0; nt < 4; nt++) {
            int r = m0 + wm + mt * 16 + g;
            int c = n0 + wn + nt * 8 + 2 * tg;
            float2 bb = *reinterpret_cast<const float2*>(bias + c);
            float2 v0 = {acc[mt][nt][0] + bb.x, acc[mt][nt][1] + bb.y};
            float2 v1 = {acc[mt][nt][2] + bb.x, acc[mt][nt][3] + bb.y};
            *reinterpret_cast<float2*>(C + (size_t)r * N + c) = v0;
            *reinterpret_cast<float2*>(C + (size_t)(r + 8) * N + c) = v1;
        }
    }
}

// =============================================================================
// Persistent LSTM recurrence (R15 config — best measured) + idle-SM pipelined
// Wout transpose. 148 CTAs, 1 CTA/SM:
//   bids 0..127  : recurrence (grid barrier counts exactly 128 arrivals)
//   bids 128..147: grid-stride Wout [H,V]->[V,H] fp16 transpose with
//                  register prefetch + double-buffered smem, 1 sync/tile.
// =============================================================================
#define NCTA2 128
#define TRANS_CTAS 20
#define WR_STRIDE 516
#define HS_STRIDE 516
#define WR_WORDS (32 * WR_STRIDE)    // 16512
#define HS_WORDS (B_ * HS_STRIDE)    // 8256
#define ZS_STRIDE 33
#define ZS_WARP (16 * ZS_STRIDE)     // 528
#define ZS_FLOATS (8 * ZS_WARP)      // 4224
#define RECUR_SMEM ((WR_WORDS + HS_WORDS + ZS_FLOATS) * 4)  // 115968 B

__global__ void __launch_bounds__(256, 1)
lstm_recur(const float* __restrict__ rec, const float* __restrict__ wout,
           __half* __restrict__ woutT) {
    extern __shared__ uint32_t sm2[];

    const int tid  = threadIdx.x;
    const int lane = tid & 31;
    const int wid  = tid >> 5;

    // -------- transpose CTAs: pipelined, 1 sync/tile, LDG prefetch ----------
    if (blockIdx.x >= NCTA2) {
        float (*tb)[32][33] = reinterpret_cast<float(*)[32][33]>(sm2);
        const int tx = tid & 31, ty = tid >> 5;        // 32 x 8
        const int NBX = V_ / 32;                       // 1000 tiles in n
        const int NTOT = NBX * (H_ / 32);              // 32000 tiles

        int t = blockIdx.x - NCTA2;
        float r[4];
        if (t < NTOT) {
            int n0 = (t % NBX) * 32, k0 = (t / NBX) * 32;
#pragma unroll
            for (int i = 0; i < 4; i++)
                r[i] = wout[(size_t)(k0 + ty + i * 8) * V_ + n0 + tx];
        }
        int p = 0;
        while (t < NTOT) {
#pragma unroll
            for (int i = 0; i < 4; i++) tb[p][ty + i * 8][tx] = r[i];
            const int tn = t + TRANS_CTAS;
            if (tn < NTOT) {      // prefetch next tile while this one drains
                int n0 = (tn % NBX) * 32, k0 = (tn / NBX) * 32;
#pragma unroll
                for (int i = 0; i < 4; i++)
                    r[i] = wout[(size_t)(k0 + ty + i * 8) * V_ + n0 + tx];
            }
            __syncthreads();
            {
                int n0 = (t % NBX) * 32, k0 = (t / NBX) * 32;
#pragma unroll
                for (int i = 0; i < 4; i++)
                    woutT[(size_t)(n0 + ty + i * 8) * H_ + k0 + tx] =
                        __float2half_rn(tb[p][tx][ty + i * 8]);
            }
            p ^= 1;
            t = tn;
        }
        return;
    }

    // -------- recurrence CTAs (byte-identical logic to R15) -----------------
    uint32_t* Wr2 = sm2;                       // [32 n][512 kp] stride 516
    uint32_t* Hs  = sm2 + WR_WORDS;            // [16 b][512 kp] stride 516
    float* Zs = reinterpret_cast<float*>(sm2 + WR_WORDS + HS_WORDS);

    uint32_t sb2;
    asm("{.reg .u64 t; cvta.to.shared.u64 t, %1; cvt.u32.u64 %0, t;}"
        : "=r"(sb2) : "l"(sm2));

    const int j0 = blockIdx.x * 8;
    const int g  = lane >> 2;
    const int tg = lane & 3;
    const int l7 = lane & 7;
    const int hb = (lane >> 3) & 1;
    const int hc = lane >> 4;

    // load Wr slice once: Wr2[n][kp] = packed k-pair, n -> (n/8)*H + j0 + (n&7)
    for (int i = tid; i < 32 * 512; i += 256) {
        int kp = i >> 5, n = i & 31;
        int gcol = (n >> 3) * H_ + j0 + (n & 7);
        float v0 = rec[(size_t)(2 * kp) * FH + gcol];
        float v1 = rec[(size_t)(2 * kp + 1) * FH + gcol];
        Wr2[n * WR_STRIDE + kp] = pack2h(v0, v1);
    }

    const int kw0 = wid * 64;
    const uint32_t a_base = sb2
        + (uint32_t)(WR_WORDS + (lane & 15) * HS_STRIDE + kw0) * 4
        + (uint32_t)((lane >> 4) * 16);
    const uint32_t b_base0 = sb2
        + (uint32_t)((l7 + hb * 8) * WR_STRIDE + kw0) * 4 + (uint32_t)(hc * 16);
    const uint32_t b_base1 = b_base0 + (uint32_t)(16 * WR_STRIDE * 4);

    __syncthreads();

    // persistent B fragments: Br[kt][nt][2], 64 regs
    uint32_t Br[8][4][2];
#pragma unroll
    for (int kt = 0; kt < 8; ++kt) {
        ldsm4(Br[kt][0][0], Br[kt][1][0], Br[kt][0][1], Br[kt][1][1],
              b_base0 + kt * 32);
        ldsm4(Br[kt][2][0], Br[kt][3][0], Br[kt][2][1], Br[kt][3][1],
              b_base1 + kt * 32);
    }

    const int gb = tid >> 3;
    const int gj = tid & 7;
    float creg = 0.0f;

    // prefetch zx for step 0
    float zxi = 0.f, zxf = 0.f, zxg = 0.f, zxo = 0.f;
    if (tid < 128) {
        const float* zx = g_zx + (size_t)gb * FH + j0 + gj;
        zxi = zx[0];
        zxf = zx[H_];
        zxg = zx[2 * H_];
        zxo = zx[3 * H_];
    }

    for (int s = 0; s < T_; ++s) {
        // stage h into shared (read buffer s&1; step 0 = zeros)
        if (s == 0) {
            for (int i = tid; i < HS_WORDS; i += 256) Hs[i] = 0u;
        } else {
            const uint32_t* gh_w = reinterpret_cast<const uint32_t*>(g_hbuf[s & 1]);
#pragma unroll
            for (int i = 0; i < 8; ++i) {
                int idx = tid + i * 256;   // 0..2047 uint4s
                int b = idx >> 7, q = idx & 127;
                uint4 v = *reinterpret_cast<const uint4*>(gh_w + b * 512 + q * 4);
                *reinterpret_cast<uint4*>(Hs + b * HS_STRIDE + q * 4) = v;
            }
        }
        __syncthreads();

        // partial z = h @ Wr over this warp's k-eighth, all 32 n
        float ac[4][4];
#pragma unroll
        for (int i = 0; i < 4; i++)
#pragma unroll
            for (int j = 0; j < 4; j++) ac[i][j] = 0.0f;

#pragma unroll
        for (int kt = 0; kt < 8; ++kt) {
            uint32_t a0, a1, a2, a3;
            ldsm4(a0, a1, a2, a3, a_base + kt * 32);
#pragma unroll
            for (int nt = 0; nt < 4; ++nt)
                mma_f16(ac[nt], a0, a1, a2, a3, Br[kt][nt][0], Br[kt][nt][1]);
        }

        float* zp = Zs + wid * ZS_WARP;
#pragma unroll
        for (int nt = 0; nt < 4; ++nt) {
            zp[g * ZS_STRIDE + nt * 8 + 2 * tg]           = ac[nt][0];
            zp[g * ZS_STRIDE + nt * 8 + 2 * tg + 1]       = ac[nt][1];
            zp[(g + 8) * ZS_STRIDE + nt * 8 + 2 * tg]     = ac[nt][2];
            zp[(g + 8) * ZS_STRIDE + nt * 8 + 2 * tg + 1] = ac[nt][3];
        }
        __syncthreads();

        // gates + state update (128 threads: (b, jj))
        if (tid < 128) {
            float zi = zxi, zf = zxf, zg = zxg, zo = zxo;
#pragma unroll
            for (int w = 0; w < 8; ++w) {
                const float* zr = Zs + w * ZS_WARP + gb * ZS_STRIDE + gj;
                zi += zr[0];
                zf += zr[8];
                zg += zr[16];
                zo += zr[24];
            }
            creg = sigfast(zf) * creg + sigfast(zi) * tanhfast(zg);
            float hh = sigfast(zo) * tanhfast(creg);
            __half hv = __float2half_rn(hh);
            g_hbuf[(s + 1) & 1][gb * H_ + j0 + gj] = hv;
            g_hseq[((size_t)gb * T_ + s) * H_ + j0 + gj] = hv;
        }
        __syncthreads();

        // arrive; prefetch zx[s+1] while the barrier drains; then poll
        if (tid == 0) {
            asm volatile("red.release.gpu.global.add.u32 [%0], %1;" ::
                         "l"(&g_bar_count), "r"(1u) : "memory");
        }
        float nzxi = 0.f, nzxf = 0.f, nzxg = 0.f, nzxo = 0.f;
        if (tid < 128 && s + 1 < T_) {
            const float* zx = g_zx + ((size_t)(s + 1) * B_ + gb) * FH + j0 + gj;
            nzxi = zx[0];
            nzxf = zx[H_];
            nzxg = zx[2 * H_];
            nzxo = zx[3 * H_];
        }
        if (tid == 0) {
            unsigned target = (unsigned)NCTA2 * (unsigned)(s + 1);
            unsigned v;
            do {
                asm volatile("ld.acquire.gpu.global.u32 %0, [%1];"
                             : "=r"(v) : "l"(&g_bar_count) : "memory");
            } while (v < target);
        }
        __syncthreads();
        zxi = nzxi;
        zxf = nzxf;
        zxg = nzxg;
        zxo = nzxo;
    }
}

// =============================================================================
// host
// =============================================================================
extern "C" void kernel_launch(void* const* d_in, const int* in_sizes, int n_in,
                              void* d_out, int out_size) {
    (void)in_sizes; (void)n_in; (void)out_size;
    const int*   x    = (const int*)d_in[0];
    const float* emb  = (const float*)d_in[1];
    const float* W    = (const float*)d_in[2];
    const float* Wr   = (const float*)d_in[3];
    const float* bias = (const float*)d_in[4];
    const float* Wout = (const float*)d_in[5];
    const float* bout = (const float*)d_in[6];
    float* out = (float*)d_out;

    cudaFuncSetAttribute(gemm_ld,    cudaFuncAttributeMaxDynamicSharedMemorySize, GEMM_SMEM);
    cudaFuncSetAttribute(lstm_recur, cudaFuncAttributeMaxDynamicSharedMemorySize, RECUR_SMEM);

    float* zx_p = nullptr;
    __half *hseq_p = nullptr, *a16_p = nullptr, *wT_p = nullptr, *woutT_p = nullptr;
    unsigned* bar_p = nullptr;
    cudaGetSymbolAddress((void**)&zx_p, g_zx);
    cudaGetSymbolAddress((void**)&hseq_p, g_hseq);
    cudaGetSymbolAddress((void**)&a16_p, g_a16);
    cudaGetSymbolAddress((void**)&wT_p, g_wT);
    cudaGetSymbolAddress((void**)&woutT_p, g_woutT);
    cudaGetSymbolAddress((void**)&bar_p, g_bar_count);

    // reset grid-barrier counter (graph-capturable)
    cudaMemsetAsync(bar_p, 0, sizeof(unsigned));

    // preproc: gather+convert embedding rows; transpose kernel W (tiny).
    // Wout transpose is folded into K2's idle SMs.
    gather_cvt<<<(BT * E_ / 4) / 256, 256>>>(x, (const float4*)emb, (uint2*)a16_p);
    transpose_f16<<<dim3(FH / 32, E_ / 32), 256>>>(W, wT_p, E_, FH);

    // K1: zx[t*B+b][4H] = a16 @ kernel + bias   (M=4096, N=4096, K=512)
    gemm_ld<<<dim3(BT / GTM, FH / GTN), 256, GEMM_SMEM>>>(
        (const uint32_t*)a16_p, (const uint32_t*)wT_p, bias, zx_p, BT, FH, E_);

    // K2: LSTM recurrence (CTAs 0..127) + pipelined Wout transpose (128..147)
    lstm_recur<<<NCTA2 + TRANS_CTAS, 256, RECUR_SMEM>>>(Wr, Wout, woutT_p);

    // K3: logits[b*T+t][V] = hseq @ w_out + b_out   (M=4096, N=32000, K=1024)
    gemm_ld<<<dim3(BT / GTM, V_ / GTN), 256, GEMM_SMEM>>>(
        (const uint32_t*)hseq_p, (const uint32_t*)woutT_p, bout, out, BT, V_, H_);
}

// round 17
// speedup vs baseline: 1.1653x; 1.1653x over previous
#include <cuda_runtime.h>
#include <cuda_fp16.h>
#include <cstdint>

#define V_  32000
#define E_  512
#define H_  1024
#define B_  16
#define T_  256
#define BT  4096
#define FH  4096

// ---------------- scratch (device globals; no allocation allowed) -----------
__device__ float  g_zx[(size_t)BT * FH];                    // [t][b][4H] 64MB
__device__ __align__(16) __half g_hseq[(size_t)BT * H_];    // [b][t][H] fp16 8MB
__device__ __align__(16) __half g_hbuf[2][B_ * H_];         // double-buffered h
__device__ __align__(16) __half g_a16[(size_t)BT * E_];     // gathered emb fp16 4MB
__device__ __align__(16) __half g_wT[(size_t)FH * E_];      // kernel^T [4H,E]
__device__ __align__(16) __half g_woutT[(size_t)V_ * H_];   // w_out^T [V,H]
__device__ unsigned g_bar_count;

// ---------------- helpers ----------------------------------------------------
__device__ __forceinline__ uint32_t pack2h(float a, float b) {
    __half2 h = __floats2half2_rn(a, b);
    return *reinterpret_cast<uint32_t*>(&h);
}

__device__ __forceinline__ void mma_f16(float* c,
                                        uint32_t a0, uint32_t a1, uint32_t a2, uint32_t a3,
                                        uint32_t b0, uint32_t b1) {
    asm volatile(
        "mma.sync.aligned.m16n8k16.row.col.f32.f16.f16.f32 "
        "{%0,%1,%2,%3}, {%4,%5,%6,%7}, {%8,%9}, {%0,%1,%2,%3};"
        : "+f"(c[0]), "+f"(c[1]), "+f"(c[2]), "+f"(c[3])
        : "r"(a0), "r"(a1), "r"(a2), "r"(a3), "r"(b0), "r"(b1));
}

__device__ __forceinline__ void ldsm4(uint32_t& r0, uint32_t& r1, uint32_t& r2,
                                      uint32_t& r3, uint32_t addr) {
    asm volatile("ldmatrix.sync.aligned.m8n8.x4.shared.b16 {%0,%1,%2,%3}, [%4];"
                 : "=r"(r0), "=r"(r1), "=r"(r2), "=r"(r3) : "r"(addr));
}

__device__ __forceinline__ float tanhfast(float x) {
    float y;
    asm("tanh.approx.f32 %0, %1;" : "=f"(y) : "f"(x));
    return y;
}
__device__ __forceinline__ float sigfast(float x) {
    return fmaf(tanhfast(0.5f * x), 0.5f, 0.5f);
}

__device__ __forceinline__ void cp16(uint32_t dst, const void* src) {
    asm volatile("cp.async.cg.shared.global [%0], [%1], 16;\n" ::
                 "r"(dst), "l"(src) : "memory");
}
__device__ __forceinline__ void cp_commit() {
    asm volatile("cp.async.commit_group;" ::: "memory");
}
template <int N>
__device__ __forceinline__ void cp_wait() {
    asm volatile("cp.async.wait_group %0;" :: "n"(N) : "memory");
}

// ---------------- gathered embedding -> fp16 ----------------------------------
__global__ void __launch_bounds__(256)
gather_cvt(const int* __restrict__ xs, const float4* __restrict__ emb,
           uint2* __restrict__ dst) {
    int i = blockIdx.x * blockDim.x + threadIdx.x;   // 0 .. BT*E/4-1
    int r = i >> 7;             // row (E/4 = 128 float4s per row)
    int c = i & 127;
    int src = xs[(r & (B_ - 1)) * T_ + (r >> 4)];
    float4 v = emb[(size_t)src * (E_ / 4) + c];
    uint2 o;
    o.x = pack2h(v.x, v.y);
    o.y = pack2h(v.z, v.w);
    dst[i] = o;
}

// ---------------- fp32 [K,N] -> fp16 [N,K] transpose (for kernel W only) -------
__global__ void __launch_bounds__(256)
transpose_f16(const float* __restrict__ src, __half* __restrict__ dst, int K, int N) {
    __shared__ float tile[32][33];
    int n0 = blockIdx.x * 32, k0 = blockIdx.y * 32;
    int tx = threadIdx.x & 31, ty = threadIdx.x >> 5;  // 32 x 8
#pragma unroll
    for (int i = 0; i < 4; i++)
        tile[ty + i * 8][tx] = src[(size_t)(k0 + ty + i * 8) * N + n0 + tx];
    __syncthreads();
#pragma unroll
    for (int i = 0; i < 4; i++)
        dst[(size_t)(n0 + ty + i * 8) * K + k0 + tx] = __float2half_rn(tile[tx][ty + i * 8]);
}

// =============================================================================
// Pipelined fp16 GEMM (f32 accum), ldmatrix operand fetch. (R8/R10 config)
//   C[M,N] = A[M,K] @ Bt[N,K]^T + bias[N]
// CTA tile 128x128, k-tile 64, PS=3, 256 threads = 8 warps (2m x 4n of 64x32).
// 2 CTAs/SM. blockIdx.x = m (fast).
// =============================================================================
#define GTM 128
#define GTN 128
#define GTK 64
#define PS  3
#define A_BYTES (128 * 128)              // 16KB
#define ST_BYTES (2 * A_BYTES)           // 32KB
#define GEMM_SMEM (PS * ST_BYTES)        // 98304 B

__global__ void __launch_bounds__(256, 2)
gemm_ld(const uint32_t* __restrict__ A, const uint32_t* __restrict__ Bt,
        const float* __restrict__ bias, float* __restrict__ C,
        int M, int N, int K) {
    extern __shared__ uint32_t sm[];
    uint32_t sb;
    asm("{.reg .u64 t; cvta.to.shared.u64 t, %1; cvt.u32.u64 %0, t;}"
        : "=r"(sb) : "l"(sm));

    const int tid  = threadIdx.x;
    const int lane = tid & 31;
    const int wid  = tid >> 5;
    const int m0   = blockIdx.x * GTM;
    const int n0   = blockIdx.y * GTN;
    const int wm   = (wid & 1) * 64;
    const int wn   = (wid >> 1) * 32;
    const int g    = lane >> 2;
    const int tg   = lane & 3;
    const int Kw   = K >> 1;              // 32-bit words per row

    float acc[4][4][4];
#pragma unroll
    for (int i = 0; i < 4; i++)
#pragma unroll
        for (int j = 0; j < 4; j++)
#pragma unroll
            for (int k = 0; k < 4; k++) acc[i][j][k] = 0.0f;

    const int lr = tid >> 3;      // base row 0..31 (stride 32)
    const int lc = tid & 7;       // chunk 0..7
    const uint32_t sw_off = (uint32_t)(lr * 128 + ((lc ^ (lr & 7)) * 16));

    const uint32_t* aptr[4];
#pragma unroll
    for (int i = 0; i < 4; i++)
        aptr[i] = A + (size_t)(m0 + lr + i * 32) * Kw + lc * 4;
    const uint32_t* bptr = Bt + (size_t)(n0 + lr) * Kw + lc * 4;
    const size_t bstep = (size_t)32 * Kw;

    const int KT = K / GTK;

    auto load_stage = [&](int st, int kt) {
        const int k0w = kt * (GTK / 2);
        const uint32_t ab = sb + st * ST_BYTES + sw_off;
        const uint32_t bb = ab + A_BYTES;
#pragma unroll
        for (int i = 0; i < 4; i++) cp16(ab + i * 32 * 128, aptr[i] + k0w);
        const uint32_t* bp = bptr + k0w;
#pragma unroll
        for (int i = 0; i < 4; i++) { cp16(bb + i * 32 * 128, bp); bp += bstep; }
    };

    const int l7 = lane & 7;
    const int hb = (lane >> 3) & 1;
    const int hc = lane >> 4;
    uint32_t a_row_off[4], b_row_off[2];
#pragma unroll
    for (int mt = 0; mt < 4; mt++)
        a_row_off[mt] = (uint32_t)((wm + mt * 16 + l7 + hb * 8) * 128);
#pragma unroll
    for (int p = 0; p < 2; p++)
        b_row_off[p] = (uint32_t)(A_BYTES + (wn + p * 16 + l7 + hb * 8) * 128);
    uint32_t choff[4];
#pragma unroll
    for (int kk = 0; kk < 4; kk++)
        choff[kk] = (uint32_t)((((2 * kk + hc) ^ l7)) * 16);

#pragma unroll
    for (int p = 0; p < PS - 1; ++p) {
        load_stage(p, p);
        cp_commit();
    }

    for (int kt = 0; kt < KT; ++kt) {
        cp_wait<PS - 2>();
        __syncthreads();
        if (kt + PS - 1 < KT) load_stage((kt + PS - 1) % PS, kt + PS - 1);
        cp_commit();

        const uint32_t st = sb + (uint32_t)(kt % PS) * ST_BYTES;
#pragma unroll
        for (int kk = 0; kk < 4; kk++) {   // each kk = 16 K-elements
            const uint32_t co = choff[kk];
            uint32_t bf[4][2];
            ldsm4(bf[0][0], bf[1][0], bf[0][1], bf[1][1], st + b_row_off[0] + co);
            ldsm4(bf[2][0], bf[3][0], bf[2][1], bf[3][1], st + b_row_off[1] + co);
#pragma unroll
            for (int mt = 0; mt < 4; mt++) {
                uint32_t a0, a1, a2, a3;
                ldsm4(a0, a1, a2, a3, st + a_row_off[mt] + co);
#pragma unroll
                for (int nt = 0; nt < 4; nt++)
                    mma_f16(acc[mt][nt], a0, a1, a2, a3, bf[nt][0], bf[nt][1]);
            }
        }
    }

#pragma unroll
    for (int mt = 0; mt < 4; mt++) {
#pragma unroll
        for (int nt = 0; nt < 4; nt++) {
            int r = m0 + wm + mt * 16 + g;
            int c = n0 + wn + nt * 8 + 2 * tg;
            float2 bb = *reinterpret_cast<const float2*>(bias + c);
            float2 v0 = {acc[mt][nt][0] + bb.x, acc[mt][nt][1] + bb.y};
            float2 v1 = {acc[mt][nt][2] + bb.x, acc[mt][nt][3] + bb.y};
            *reinterpret_cast<float2*>(C + (size_t)r * N + c) = v0;
            *reinterpret_cast<float2*>(C + (size_t)(r + 8) * N + c) = v1;
        }
    }
}

// =============================================================================
// Persistent LSTM recurrence (R15 config — best measured) + idle-SM grouped
// Wout transpose. 148 CTAs, 1 CTA/SM:
//   bids 0..127  : recurrence (grid barrier counts exactly 128 arrivals)
//   bids 128..147: Wout [H,V]->[V,H] fp16 transpose, groups of 4 tiles with
//                  all 16 LDGs issued up-front (MLP covers DRAM latency),
//                  double-buffered smem, 1 sync per tile.
// =============================================================================
#define NCTA2 128
#define TRANS_CTAS 20
#define TG 4
#define WR_STRIDE 516
#define HS_STRIDE 516
#define WR_WORDS (32 * WR_STRIDE)    // 16512
#define HS_WORDS (B_ * HS_STRIDE)    // 8256
#define ZS_STRIDE 33
#define ZS_WARP (16 * ZS_STRIDE)     // 528
#define ZS_FLOATS (8 * ZS_WARP)      // 4224
#define RECUR_SMEM ((WR_WORDS + HS_WORDS + ZS_FLOATS) * 4)  // 115968 B

__global__ void __launch_bounds__(256, 1)
lstm_recur(const float* __restrict__ rec, const float* __restrict__ wout,
           __half* __restrict__ woutT) {
    extern __shared__ uint32_t sm2[];

    const int tid  = threadIdx.x;
    const int lane = tid & 31;
    const int wid  = tid >> 5;

    // -------- transpose CTAs: grouped MLP loads, 1 sync/tile ----------------
    if (blockIdx.x >= NCTA2) {
        float (*tb)[32][33] = reinterpret_cast<float(*)[32][33]>(sm2);
        const int tx = tid & 31, ty = tid >> 5;        // 32 x 8
        const int NBX = V_ / 32;                       // 1000 tiles in n
        const int NTOT = NBX * (H_ / 32);              // 32000 (divisible by 80)
        const int bid = blockIdx.x - NCTA2;

        int p = 0;
        for (int base = bid * TG; base < NTOT; base += TRANS_CTAS * TG) {
            // phase A: issue ALL group loads back-to-back (MLP = 16)
            float r[TG][4];
#pragma unroll
            for (int j = 0; j < TG; j++) {
                int t = base + j;
                int n0 = (t % NBX) * 32, k0 = (t / NBX) * 32;
#pragma unroll
                for (int i = 0; i < 4; i++)
                    r[j][i] = wout[(size_t)(k0 + ty + i * 8) * V_ + n0 + tx];
            }
            // phase B: drain tiles through double-buffered smem
#pragma unroll
            for (int j = 0; j < TG; j++) {
                int t = base + j;
#pragma unroll
                for (int i = 0; i < 4; i++) tb[p][ty + i * 8][tx] = r[j][i];
                __syncthreads();
                int n0 = (t % NBX) * 32, k0 = (t / NBX) * 32;
#pragma unroll
                for (int i = 0; i < 4; i++)
                    woutT[(size_t)(n0 + ty + i * 8) * H_ + k0 + tx] =
                        __float2half_rn(tb[p][tx][ty + i * 8]);
                p ^= 1;
            }
        }
        return;
    }

    // -------- recurrence CTAs (byte-identical logic to R15) -----------------
    uint32_t* Wr2 = sm2;                       // [32 n][512 kp] stride 516
    uint32_t* Hs  = sm2 + WR_WORDS;            // [16 b][512 kp] stride 516
    float* Zs = reinterpret_cast<float*>(sm2 + WR_WORDS + HS_WORDS);

    uint32_t sb2;
    asm("{.reg .u64 t; cvta.to.shared.u64 t, %1; cvt.u32.u64 %0, t;}"
        : "=r"(sb2) : "l"(sm2));

    const int j0 = blockIdx.x * 8;
    const int g  = lane >> 2;
    const int tg = lane & 3;
    const int l7 = lane & 7;
    const int hb = (lane >> 3) & 1;
    const int hc = lane >> 4;

    // load Wr slice once: Wr2[n][kp] = packed k-pair, n -> (n/8)*H + j0 + (n&7)
    for (int i = tid; i < 32 * 512; i += 256) {
        int kp = i >> 5, n = i & 31;
        int gcol = (n >> 3) * H_ + j0 + (n & 7);
        float v0 = rec[(size_t)(2 * kp) * FH + gcol];
        float v1 = rec[(size_t)(2 * kp + 1) * FH + gcol];
        Wr2[n * WR_STRIDE + kp] = pack2h(v0, v1);
    }

    const int kw0 = wid * 64;
    const uint32_t a_base = sb2
        + (uint32_t)(WR_WORDS + (lane & 15) * HS_STRIDE + kw0) * 4
        + (uint32_t)((lane >> 4) * 16);
    const uint32_t b_base0 = sb2
        + (uint32_t)((l7 + hb * 8) * WR_STRIDE + kw0) * 4 + (uint32_t)(hc * 16);
    const uint32_t b_base1 = b_base0 + (uint32_t)(16 * WR_STRIDE * 4);

    __syncthreads();

    // persistent B fragments: Br[kt][nt][2], 64 regs
    uint32_t Br[8][4][2];
#pragma unroll
    for (int kt = 0; kt < 8; ++kt) {
        ldsm4(Br[kt][0][0], Br[kt][1][0], Br[kt][0][1], Br[kt][1][1],
              b_base0 + kt * 32);
        ldsm4(Br[kt][2][0], Br[kt][3][0], Br[kt][2][1], Br[kt][3][1],
              b_base1 + kt * 32);
    }

    const int gb = tid >> 3;
    const int gj = tid & 7;
    float creg = 0.0f;

    // prefetch zx for step 0
    float zxi = 0.f, zxf = 0.f, zxg = 0.f, zxo = 0.f;
    if (tid < 128) {
        const float* zx = g_zx + (size_t)gb * FH + j0 + gj;
        zxi = zx[0];
        zxf = zx[H_];
        zxg = zx[2 * H_];
        zxo = zx[3 * H_];
    }

    for (int s = 0; s < T_; ++s) {
        // stage h into shared (read buffer s&1; step 0 = zeros)
        if (s == 0) {
            for (int i = tid; i < HS_WORDS; i += 256) Hs[i] = 0u;
        } else {
            const uint32_t* gh_w = reinterpret_cast<const uint32_t*>(g_hbuf[s & 1]);
#pragma unroll
            for (int i = 0; i < 8; ++i) {
                int idx = tid + i * 256;   // 0..2047 uint4s
                int b = idx >> 7, q = idx & 127;
                uint4 v = *reinterpret_cast<const uint4*>(gh_w + b * 512 + q * 4);
                *reinterpret_cast<uint4*>(Hs + b * HS_STRIDE + q * 4) = v;
            }
        }
        __syncthreads();

        // partial z = h @ Wr over this warp's k-eighth, all 32 n
        float ac[4][4];
#pragma unroll
        for (int i = 0; i < 4; i++)
#pragma unroll
            for (int j = 0; j < 4; j++) ac[i][j] = 0.0f;

#pragma unroll
        for (int kt = 0; kt < 8; ++kt) {
            uint32_t a0, a1, a2, a3;
            ldsm4(a0, a1, a2, a3, a_base + kt * 32);
#pragma unroll
            for (int nt = 0; nt < 4; ++nt)
                mma_f16(ac[nt], a0, a1, a2, a3, Br[kt][nt][0], Br[kt][nt][1]);
        }

        float* zp = Zs + wid * ZS_WARP;
#pragma unroll
        for (int nt = 0; nt < 4; ++nt) {
            zp[g * ZS_STRIDE + nt * 8 + 2 * tg]           = ac[nt][0];
            zp[g * ZS_STRIDE + nt * 8 + 2 * tg + 1]       = ac[nt][1];
            zp[(g + 8) * ZS_STRIDE + nt * 8 + 2 * tg]     = ac[nt][2];
            zp[(g + 8) * ZS_STRIDE + nt * 8 + 2 * tg + 1] = ac[nt][3];
        }
        __syncthreads();

        // gates + state update (128 threads: (b, jj))
        if (tid < 128) {
            float zi = zxi, zf = zxf, zg = zxg, zo = zxo;
#pragma unroll
            for (int w = 0; w < 8; ++w) {
                const float* zr = Zs + w * ZS_WARP + gb * ZS_STRIDE + gj;
                zi += zr[0];
                zf += zr[8];
                zg += zr[16];
                zo += zr[24];
            }
            creg = sigfast(zf) * creg + sigfast(zi) * tanhfast(zg);
            float hh = sigfast(zo) * tanhfast(creg);
            __half hv = __float2half_rn(hh);
            g_hbuf[(s + 1) & 1][gb * H_ + j0 + gj] = hv;
            g_hseq[((size_t)gb * T_ + s) * H_ + j0 + gj] = hv;
        }
        __syncthreads();

        // arrive; prefetch zx[s+1] while the barrier drains; then poll
        if (tid == 0) {
            asm volatile("red.release.gpu.global.add.u32 [%0], %1;" ::
                         "l"(&g_bar_count), "r"(1u) : "memory");
        }
        float nzxi = 0.f, nzxf = 0.f, nzxg = 0.f, nzxo = 0.f;
        if (tid < 128 && s + 1 < T_) {
            const float* zx = g_zx + ((size_t)(s + 1) * B_ + gb) * FH + j0 + gj;
            nzxi = zx[0];
            nzxf = zx[H_];
            nzxg = zx[2 * H_];
            nzxo = zx[3 * H_];
        }
        if (tid == 0) {
            unsigned target = (unsigned)NCTA2 * (unsigned)(s + 1);
            unsigned v;
            do {
                asm volatile("ld.acquire.gpu.global.u32 %0, [%1];"
                             : "=r"(v) : "l"(&g_bar_count) : "memory");
            } while (v < target);
        }
        __syncthreads();
        zxi = nzxi;
        zxf = nzxf;
        zxg = nzxg;
        zxo = nzxo;
    }
}

// =============================================================================
// host
// =============================================================================
extern "C" void kernel_launch(void* const* d_in, const int* in_sizes, int n_in,
                              void* d_out, int out_size) {
    (void)in_sizes; (void)n_in; (void)out_size;
    const int*   x    = (const int*)d_in[0];
    const float* emb  = (const float*)d_in[1];
    const float* W    = (const float*)d_in[2];
    const float* Wr   = (const float*)d_in[3];
    const float* bias = (const float*)d_in[4];
    const float* Wout = (const float*)d_in[5];
    const float* bout = (const float*)d_in[6];
    float* out = (float*)d_out;

    cudaFuncSetAttribute(gemm_ld,    cudaFuncAttributeMaxDynamicSharedMemorySize, GEMM_SMEM);
    cudaFuncSetAttribute(lstm_recur, cudaFuncAttributeMaxDynamicSharedMemorySize, RECUR_SMEM);

    float* zx_p = nullptr;
    __half *hseq_p = nullptr, *a16_p = nullptr, *wT_p = nullptr, *woutT_p = nullptr;
    unsigned* bar_p = nullptr;
    cudaGetSymbolAddress((void**)&zx_p, g_zx);
    cudaGetSymbolAddress((void**)&hseq_p, g_hseq);
    cudaGetSymbolAddress((void**)&a16_p, g_a16);
    cudaGetSymbolAddress((void**)&wT_p, g_wT);
    cudaGetSymbolAddress((void**)&woutT_p, g_woutT);
    cudaGetSymbolAddress((void**)&bar_p, g_bar_count);

    // reset grid-barrier counter (graph-capturable)
    cudaMemsetAsync(bar_p, 0, sizeof(unsigned));

    // preproc: gather+convert embedding rows; transpose kernel W (tiny).
    // Wout transpose is folded into K2's idle SMs.
    gather_cvt<<<(BT * E_ / 4) / 256, 256>>>(x, (const float4*)emb, (uint2*)a16_p);
    transpose_f16<<<dim3(FH / 32, E_ / 32), 256>>>(W, wT_p, E_, FH);

    // K1: zx[t*B+b][4H] = a16 @ kernel + bias   (M=4096, N=4096, K=512)
    gemm_ld<<<dim3(BT / GTM, FH / GTN), 256, GEMM_SMEM>>>(
        (const uint32_t*)a16_p, (const uint32_t*)wT_p, bias, zx_p, BT, FH, E_);

    // K2: LSTM recurrence (CTAs 0..127) + grouped Wout transpose (128..147)
    lstm_recur<<<NCTA2 + TRANS_CTAS, 256, RECUR_SMEM>>>(Wr, Wout, woutT_p);

    // K3: logits[b*T+t][V] = hseq @ w_out + b_out   (M=4096, N=32000, K=1024)
    gemm_ld<<<dim3(BT / GTM, V_ / GTN), 256, GEMM_SMEM>>>(
        (const uint32_t*)hseq_p, (const uint32_t*)woutT_p, bout, out, BT, V_, H_);
}